// round 4
// baseline (speedup 1.0000x reference)
#include <cuda_runtime.h>
#include <cstdint>
#include <math.h>

#define BATCH 4
#define SEQ   1024
#define DM    1024
#define DI    2048
#define DS    16
#define DTRK  64
#define NXC   96            // DT_RANK + 2*D_STATE
#define BL    (BATCH*SEQ)   // 4096

// ---------------------------------------------------------------------------
// Scratch (static __device__ globals — no allocation anywhere)
// ---------------------------------------------------------------------------
__device__ float g_normed[(size_t)BL * DM];        // 16 MB
__device__ float g_xz[(size_t)BL * 2 * DI];        // 64 MB  (xi | z)
__device__ float g_xc[(size_t)BL * DI];            // 32 MB
__device__ float g_xdbl[(size_t)BL * NXC];         // 1.5 MB (dt_r | B | C)
__device__ float g_dt[(size_t)BL * DI];            // 32 MB
__device__ float g_y[(size_t)BL * DI];             // 32 MB

// ---------------------------------------------------------------------------
// Helpers
// ---------------------------------------------------------------------------
__device__ __forceinline__ unsigned f2tf(float f) {
    unsigned u;
    asm("cvt.rna.tf32.f32 %0, %1;" : "=r"(u) : "f"(f));
    return u;
}

__device__ __forceinline__ void mma8(float c[4], const unsigned a[4], const unsigned b[2]) {
    asm volatile(
        "mma.sync.aligned.m16n8k8.row.col.f32.tf32.tf32.f32 "
        "{%0,%1,%2,%3}, {%4,%5,%6,%7}, {%8,%9}, {%0,%1,%2,%3};"
        : "+f"(c[0]), "+f"(c[1]), "+f"(c[2]), "+f"(c[3])
        : "r"(a[0]), "r"(a[1]), "r"(a[2]), "r"(a[3]), "r"(b[0]), "r"(b[1]));
}

// EPI: 0 = plain store, 1 = softplus(acc + bias[col]), 2 = mask ? resid+acc : 0
template <int EPI>
__device__ __forceinline__ void store_epi(
    float* __restrict__ C, int ldc, int N, int row, int col, float v,
    const float* __restrict__ bias, const float* __restrict__ resid,
    const unsigned* __restrict__ mask)
{
    if (col >= N) return;
    float out;
    if (EPI == 0) {
        out = v;
    } else if (EPI == 1) {
        float s = v + bias[col];
        out = fmaxf(s, 0.f) + log1pf(expf(-fabsf(s)));   // stable softplus
    } else {
        out = mask[row] ? (resid[(size_t)row * ldc + col] + v) : 0.f;
    }
    C[(size_t)row * ldc + col] = out;
}

// ---------------------------------------------------------------------------
// RMSNorm: one block per (b,l) row, 256 threads, 1 float4 each
// ---------------------------------------------------------------------------
__global__ __launch_bounds__(256) void rmsnorm_kernel(
    const float* __restrict__ x, const float* __restrict__ w, float* __restrict__ o)
{
    const int row = blockIdx.x;
    const int t = threadIdx.x;
    float4 v = reinterpret_cast<const float4*>(x + (size_t)row * DM)[t];
    float ss = v.x * v.x + v.y * v.y + v.z * v.z + v.w * v.w;
    #pragma unroll
    for (int ofs = 16; ofs > 0; ofs >>= 1)
        ss += __shfl_xor_sync(0xffffffffu, ss, ofs);
    __shared__ float sw[8];
    if ((t & 31) == 0) sw[t >> 5] = ss;
    __syncthreads();
    float tot = 0.f;
    #pragma unroll
    for (int i = 0; i < 8; i++) tot += sw[i];
    float r = rsqrtf(tot * (1.f / (float)DM) + 1e-6f);
    float4 wv = reinterpret_cast<const float4*>(w)[t];
    float4 ov;
    ov.x = v.x * r * wv.x; ov.y = v.y * r * wv.y;
    ov.z = v.z * r * wv.z; ov.w = v.w * r * wv.w;
    reinterpret_cast<float4*>(o + (size_t)row * DM)[t] = ov;
}

// ---------------------------------------------------------------------------
// TF32 tensor-core GEMM:  C[M,N] = A[M,K] @ Bw[N,K]^T   (NT)
// 128x128 block tile, BK=32, 8 warps each 64x32 (4x4 m16n8 tiles).
// Requires M % 128 == 0, K % 32 == 0 (true for all call sites). N guarded.
// ---------------------------------------------------------------------------
template <int EPI>
__global__ __launch_bounds__(256) void gemm_tf32(
    const float* __restrict__ A, int lda,
    const float* __restrict__ Bw, int ldb,
    float* __restrict__ C, int ldc,
    int M, int N, int K,
    const float* __restrict__ bias,
    const float* __restrict__ resid,
    const unsigned* __restrict__ mask)
{
    __shared__ unsigned As[128][33];
    __shared__ unsigned Bs[128][33];

    const int t = threadIdx.x;
    const int m0 = blockIdx.y * 128;
    const int n0 = blockIdx.x * 128;
    const int w = t >> 5;
    const int lane = t & 31;
    const int wm = (w & 1) * 64;       // warp m-offset
    const int wn = (w >> 1) * 32;      // warp n-offset
    const int qr = lane >> 2;          // 0..7
    const int qc = lane & 3;           // 0..3
    const int lr = t >> 3;             // gmem load row 0..31 (per pass)
    const int lc = (t & 7) << 2;       // gmem load col 0..28

    float acc[4][4][4];
    #pragma unroll
    for (int i = 0; i < 4; i++)
        #pragma unroll
        for (int j = 0; j < 4; j++)
            #pragma unroll
            for (int r = 0; r < 4; r++) acc[i][j][r] = 0.f;

    for (int k0 = 0; k0 < K; k0 += 32) {
        #pragma unroll
        for (int i = 0; i < 4; i++) {
            int r = lr + i * 32;
            float4 va = *reinterpret_cast<const float4*>(
                A + (size_t)(m0 + r) * lda + k0 + lc);
            As[r][lc + 0] = f2tf(va.x);
            As[r][lc + 1] = f2tf(va.y);
            As[r][lc + 2] = f2tf(va.z);
            As[r][lc + 3] = f2tf(va.w);
            int n = n0 + r;
            float4 vb = make_float4(0.f, 0.f, 0.f, 0.f);
            if (n < N)
                vb = *reinterpret_cast<const float4*>(
                    Bw + (size_t)n * ldb + k0 + lc);
            Bs[r][lc + 0] = f2tf(vb.x);
            Bs[r][lc + 1] = f2tf(vb.y);
            Bs[r][lc + 2] = f2tf(vb.z);
            Bs[r][lc + 3] = f2tf(vb.w);
        }
        __syncthreads();

        #pragma unroll
        for (int kk = 0; kk < 32; kk += 8) {
            unsigned af[4][4], bf[4][2];
            #pragma unroll
            for (int mi = 0; mi < 4; mi++) {
                int rr = wm + mi * 16 + qr;
                af[mi][0] = As[rr][kk + qc];
                af[mi][1] = As[rr + 8][kk + qc];
                af[mi][2] = As[rr][kk + qc + 4];
                af[mi][3] = As[rr + 8][kk + qc + 4];
            }
            #pragma unroll
            for (int ni = 0; ni < 4; ni++) {
                int rr = wn + ni * 8 + qr;
                bf[ni][0] = Bs[rr][kk + qc];
                bf[ni][1] = Bs[rr][kk + qc + 4];
            }
            #pragma unroll
            for (int mi = 0; mi < 4; mi++)
                #pragma unroll
                for (int ni = 0; ni < 4; ni++)
                    mma8(acc[mi][ni], af[mi], bf[ni]);
        }
        __syncthreads();
    }

    #pragma unroll
    for (int mi = 0; mi < 4; mi++) {
        #pragma unroll
        for (int ni = 0; ni < 4; ni++) {
            int row = m0 + wm + mi * 16 + qr;
            int col = n0 + wn + ni * 8 + qc * 2;
            store_epi<EPI>(C, ldc, N, row,     col,     acc[mi][ni][0], bias, resid, mask);
            store_epi<EPI>(C, ldc, N, row,     col + 1, acc[mi][ni][1], bias, resid, mask);
            store_epi<EPI>(C, ldc, N, row + 8, col,     acc[mi][ni][2], bias, resid, mask);
            store_epi<EPI>(C, ldc, N, row + 8, col + 1, acc[mi][ni][3], bias, resid, mask);
        }
    }
}

// ---------------------------------------------------------------------------
// Depthwise causal conv (segment-gated) + SiLU.
// gate_j == (mask[l-j..l] all valid)  <=>  run >= j+1. Tap weight = conv_w[d][3-j].
// One thread handles 4 channels of one (b,l).
// ---------------------------------------------------------------------------
__global__ __launch_bounds__(256) void conv_silu_kernel(
    const float* __restrict__ xz, const float* __restrict__ cw,
    const float* __restrict__ cb, const unsigned* __restrict__ mask,
    float* __restrict__ xc)
{
    const int t = blockIdx.x * 256 + threadIdx.x;   // BL * DI/4 threads
    const int m = t >> 9;                            // row (b*L+l)
    const int c4 = (t & 511) << 2;                   // channel base
    const int l = m & (SEQ - 1);

    const float4* cw4 = reinterpret_cast<const float4*>(cw);
    float4 W0 = cw4[c4 + 0], W1 = cw4[c4 + 1], W2 = cw4[c4 + 2], W3 = cw4[c4 + 3];
    float4 acc = *reinterpret_cast<const float4*>(cb + c4);

    bool g0 = mask[m] != 0;
    bool g1 = g0 && l >= 1 && mask[m - 1] != 0;
    bool g2 = g1 && l >= 2 && mask[m - 2] != 0;
    bool g3 = g2 && l >= 3 && mask[m - 3] != 0;

    const float4* xi = reinterpret_cast<const float4*>(xz); // row stride 2*DI floats = 1024 float4
    const int base = m * 1024 + (c4 >> 2);
    if (g0) { float4 xv = xi[base];
        acc.x += W0.w * xv.x; acc.y += W1.w * xv.y; acc.z += W2.w * xv.z; acc.w += W3.w * xv.w; }
    if (g1) { float4 xv = xi[base - 1024];
        acc.x += W0.z * xv.x; acc.y += W1.z * xv.y; acc.z += W2.z * xv.z; acc.w += W3.z * xv.w; }
    if (g2) { float4 xv = xi[base - 2048];
        acc.x += W0.y * xv.x; acc.y += W1.y * xv.y; acc.z += W2.y * xv.z; acc.w += W3.y * xv.w; }
    if (g3) { float4 xv = xi[base - 3072];
        acc.x += W0.x * xv.x; acc.y += W1.x * xv.y; acc.z += W2.x * xv.z; acc.w += W3.x * xv.w; }

    float4 o;
    o.x = acc.x / (1.f + __expf(-acc.x));
    o.y = acc.y / (1.f + __expf(-acc.y));
    o.z = acc.z / (1.f + __expf(-acc.z));
    o.w = acc.w / (1.f + __expf(-acc.w));
    reinterpret_cast<float4*>(xc)[m * 512 + (c4 >> 2)] = o;
}

// ---------------------------------------------------------------------------
// Selective scan. Block = 256 threads = 16 channels x 16 states.
// Grid = B * DI/16 = 512 blocks. Each thread owns one h[d][s] over L steps.
// y = sum_s h*C (16-lane shfl reduce), then + D*x_c, * silu(z). Masked steps
// reset h to 0 (dA, dBx zeroed in reference).
// ---------------------------------------------------------------------------
__global__ __launch_bounds__(256) void scan_kernel(
    const float* __restrict__ xz, const float* __restrict__ xc,
    const float* __restrict__ xdbl, const float* __restrict__ dt,
    const float* __restrict__ A_log, const float* __restrict__ Dp,
    const unsigned* __restrict__ mask, float* __restrict__ ybuf)
{
    const int blk = blockIdx.x;
    const int b = blk >> 7;           // / (DI/16)
    const int cg = blk & 127;
    const int s = threadIdx.x & 15;
    const int ci = threadIdx.x >> 4;
    const int d = cg * 16 + ci;

    const float Aval = -expf(A_log[d * DS + s]);
    const float Dv = Dp[d];
    float h = 0.f;
    const int mbase = b * SEQ;

    for (int l = 0; l < SEQ; l++) {
        const int m = mbase + l;
        float dtv = dt[m * DI + d];
        float xv  = xc[m * DI + d];
        float Bv  = xdbl[m * NXC + DTRK + s];
        float Cv  = xdbl[m * NXC + DTRK + DS + s];
        bool mk = mask[m] != 0;
        float dA = __expf(dtv * Aval);
        h = mk ? (dA * h + dtv * Bv * xv) : 0.f;
        float yp = h * Cv;
        yp += __shfl_xor_sync(0xffffffffu, yp, 1);
        yp += __shfl_xor_sync(0xffffffffu, yp, 2);
        yp += __shfl_xor_sync(0xffffffffu, yp, 4);
        yp += __shfl_xor_sync(0xffffffffu, yp, 8);
        if (s == 0) {
            float zv = xz[m * (2 * DI) + DI + d];
            float y = yp + Dv * xv;
            ybuf[m * DI + d] = y * (zv / (1.f + __expf(-zv)));
        }
    }
}

// ---------------------------------------------------------------------------
// Launch
// ---------------------------------------------------------------------------
extern "C" void kernel_launch(void* const* d_in, const int* in_sizes, int n_in,
                              void* d_out, int out_size)
{
    (void)in_sizes; (void)n_in; (void)out_size;
    const float*    x         = (const float*)d_in[0];
    const unsigned* mask      = (const unsigned*)d_in[1];   // bool as 32-bit word, != 0
    const float*    rms_w     = (const float*)d_in[2];
    const float*    in_proj_w = (const float*)d_in[3];
    const float*    conv_w    = (const float*)d_in[4];
    const float*    conv_b    = (const float*)d_in[5];
    const float*    x_proj_w  = (const float*)d_in[6];
    const float*    dt_proj_w = (const float*)d_in[7];
    const float*    dt_proj_b = (const float*)d_in[8];
    const float*    A_log     = (const float*)d_in[9];
    const float*    Dp        = (const float*)d_in[10];
    const float*    out_proj_w= (const float*)d_in[11];
    float*          out       = (float*)d_out;

    float *normed, *xzb, *xcb, *xdblb, *dtb, *yb;
    cudaGetSymbolAddress((void**)&normed, g_normed);
    cudaGetSymbolAddress((void**)&xzb,    g_xz);
    cudaGetSymbolAddress((void**)&xcb,    g_xc);
    cudaGetSymbolAddress((void**)&xdblb,  g_xdbl);
    cudaGetSymbolAddress((void**)&dtb,    g_dt);
    cudaGetSymbolAddress((void**)&yb,     g_y);

    // 1. RMSNorm
    rmsnorm_kernel<<<BL, 256>>>(x, rms_w, normed);

    // 2. in_proj: xz[BL,4096] = normed[BL,1024] @ in_proj_w[4096,1024]^T
    gemm_tf32<0><<<dim3(32, 32), 256>>>(normed, DM, in_proj_w, DM,
                                        xzb, 2 * DI, BL, 2 * DI, DM,
                                        nullptr, nullptr, nullptr);

    // 3. segment-gated causal conv + SiLU -> x_c[BL,2048]
    conv_silu_kernel<<<(BL * (DI / 4)) / 256, 256>>>(xzb, conv_w, conv_b, mask, xcb);

    // 4. x_proj: x_dbl[BL,96] = x_c @ x_proj_w[96,2048]^T
    gemm_tf32<0><<<dim3(1, 32), 256>>>(xcb, DI, x_proj_w, DI,
                                       xdblb, NXC, BL, NXC, DI,
                                       nullptr, nullptr, nullptr);

    // 5. dt: softplus(x_dbl[:, :64] @ dt_proj_w[2048,64]^T + b) -> dt[BL,2048]
    gemm_tf32<1><<<dim3(16, 32), 256>>>(xdblb, NXC, dt_proj_w, DTRK,
                                        dtb, DI, BL, DI, DTRK,
                                        dt_proj_b, nullptr, nullptr);

    // 6. selective scan (+ D*x_c, * silu(z)) -> y[BL,2048]
    scan_kernel<<<BATCH * (DI / 16), 256>>>(xzb, xcb, xdblb, dtb, A_log, Dp, mask, yb);

    // 7. out_proj + residual + mask: out = mask ? x + y @ out_proj_w^T : 0
    gemm_tf32<2><<<dim3(8, 32), 256>>>(yb, DI, out_proj_w, DI,
                                       out, DM, BL, DM, DI,
                                       nullptr, x, mask);
}

// round 5
// speedup vs baseline: 1.8268x; 1.8268x over previous
#include <cuda_runtime.h>
#include <cstdint>
#include <math.h>

#define BATCH 4
#define SEQ   1024
#define DM    1024
#define DI    2048
#define DS    16
#define DTRK  64
#define NXC   96            // DT_RANK + 2*D_STATE
#define BL    (BATCH*SEQ)   // 4096
#define XSPLIT 8            // split-K factor for x_proj

// ---------------------------------------------------------------------------
// Scratch (static __device__ globals — no allocation anywhere)
// ---------------------------------------------------------------------------
__device__ float g_normed[(size_t)BL * DM];            // 16 MB
__device__ float g_xz[(size_t)BL * 2 * DI];            // 64 MB  (xi | z)
__device__ float g_xc[(size_t)BL * DI];                // 32 MB
__device__ float g_xdbl[(size_t)BL * NXC];             // 1.5 MB (dt_r | B | C)
__device__ float g_xpart[(size_t)XSPLIT * BL * NXC];   // 12.6 MB split-K partials
__device__ float g_dt[(size_t)BL * DI];                // 32 MB
__device__ float g_y[(size_t)BL * DI];                 // 32 MB

// ---------------------------------------------------------------------------
// Helpers
// ---------------------------------------------------------------------------
__device__ __forceinline__ void mma8(float c[4], const unsigned a[4], const unsigned b[2]) {
    asm volatile(
        "mma.sync.aligned.m16n8k8.row.col.f32.tf32.tf32.f32 "
        "{%0,%1,%2,%3}, {%4,%5,%6,%7}, {%8,%9}, {%0,%1,%2,%3};"
        : "+f"(c[0]), "+f"(c[1]), "+f"(c[2]), "+f"(c[3])
        : "r"(a[0]), "r"(a[1]), "r"(a[2]), "r"(a[3]), "r"(b[0]), "r"(b[1]));
}

// word-index swizzle inside a 128x32 tile: groups of 4 words XORed by row&7
#define SW(r, c) (((r) << 5) + ((c) ^ (((r) & 7) << 2)))

// EPI: 0 = plain store, 1 = softplus(acc + bias[col]), 2 = mask ? resid+acc : 0
template <int EPI>
__device__ __forceinline__ void store_epi(
    float* __restrict__ C, int ldc, int N, int row, int col, float v,
    const float* __restrict__ bias, const float* __restrict__ resid,
    const unsigned* __restrict__ mask)
{
    if (col >= N) return;
    float out;
    if (EPI == 0) {
        out = v;
    } else if (EPI == 1) {
        float s = v + bias[col];
        out = fmaxf(s, 0.f) + log1pf(expf(-fabsf(s)));   // stable softplus
    } else {
        out = mask[row] ? (resid[(size_t)row * ldc + col] + v) : 0.f;
    }
    C[(size_t)row * ldc + col] = out;
}

// ---------------------------------------------------------------------------
// RMSNorm: one block per (b,l) row, 256 threads, 1 float4 each
// ---------------------------------------------------------------------------
__global__ __launch_bounds__(256) void rmsnorm_kernel(
    const float* __restrict__ x, const float* __restrict__ w, float* __restrict__ o)
{
    const int row = blockIdx.x;
    const int t = threadIdx.x;
    float4 v = reinterpret_cast<const float4*>(x + (size_t)row * DM)[t];
    float ss = v.x * v.x + v.y * v.y + v.z * v.z + v.w * v.w;
    #pragma unroll
    for (int ofs = 16; ofs > 0; ofs >>= 1)
        ss += __shfl_xor_sync(0xffffffffu, ss, ofs);
    __shared__ float sw[8];
    if ((t & 31) == 0) sw[t >> 5] = ss;
    __syncthreads();
    float tot = 0.f;
    #pragma unroll
    for (int i = 0; i < 8; i++) tot += sw[i];
    float r = rsqrtf(tot * (1.f / (float)DM) + 1e-6f);
    float4 wv = reinterpret_cast<const float4*>(w)[t];
    float4 ov;
    ov.x = v.x * r * wv.x; ov.y = v.y * r * wv.y;
    ov.z = v.z * r * wv.z; ov.w = v.w * r * wv.w;
    reinterpret_cast<float4*>(o + (size_t)row * DM)[t] = ov;
}

// ---------------------------------------------------------------------------
// TF32 tensor-core GEMM:  C[M,N] = A[M,K] @ Bw[N,K]^T   (NT)
// 128x128 block tile, BK=32, 8 warps each 64x32 (4x4 m16n8 tiles).
// Double-buffered cp.async staging, XOR-swizzled smem (64 KB dynamic).
// SPLITK>1: blockIdx.z handles K-chunk z, writes partial C at offset z*M*ldc.
// Requires M % 128 == 0, K % (32*SPLITK) == 0. N guarded.
// ---------------------------------------------------------------------------
template <int EPI, int SPLITK>
__global__ __launch_bounds__(256, 2) void gemm_tf32(
    const float* __restrict__ A, int lda,
    const float* __restrict__ Bw, int ldb,
    float* __restrict__ C, int ldc,
    int M, int N, int K,
    const float* __restrict__ bias,
    const float* __restrict__ resid,
    const unsigned* __restrict__ mask)
{
    extern __shared__ float smem_f[];          // [2][4096] As | [2][4096] Bs
    float* const AsBase = smem_f;
    float* const BsBase = smem_f + 8192;
    const unsigned sAs = (unsigned)__cvta_generic_to_shared(AsBase);
    const unsigned sBs = (unsigned)__cvta_generic_to_shared(BsBase);

    const int t = threadIdx.x;
    const int m0 = blockIdx.y * 128;
    const int n0 = blockIdx.x * 128;
    const int Kc = (SPLITK > 1) ? (K / SPLITK) : K;
    const int kbase = (SPLITK > 1) ? blockIdx.z * Kc : 0;
    if (SPLITK > 1) C += (size_t)blockIdx.z * M * ldc;

    const int w = t >> 5;
    const int lane = t & 31;
    const int wm = (w & 1) * 64;       // warp m-offset
    const int wn = (w >> 1) * 32;      // warp n-offset
    const int qr = lane >> 2;          // 0..7
    const int qc = lane & 3;           // 0..3
    const int lr = t >> 3;             // gmem load row 0..31 (per pass)
    const int lc = (t & 7) << 2;       // gmem load col 0..28

    float acc[4][4][4];
    #pragma unroll
    for (int i = 0; i < 4; i++)
        #pragma unroll
        for (int j = 0; j < 4; j++)
            #pragma unroll
            for (int r = 0; r < 4; r++) acc[i][j][r] = 0.f;

    auto issue = [&](int tt, int st) {
        const int koff = kbase + tt * 32;
        #pragma unroll
        for (int i = 0; i < 4; i++) {
            const int r = lr + i * 32;
            const float* pa = A + (size_t)(m0 + r) * lda + koff + lc;
            const unsigned da = sAs + (unsigned)(st * 4096 + SW(r, lc)) * 4u;
            asm volatile("cp.async.cg.shared.global [%0], [%1], 16;\n"
                         :: "r"(da), "l"(pa));
            const int n = n0 + r;
            const float* pb = Bw + (size_t)(n < N ? n : N - 1) * ldb + koff + lc;
            const int pbytes = (n < N) ? 16 : 0;
            const unsigned db = sBs + (unsigned)(st * 4096 + SW(r, lc)) * 4u;
            asm volatile("cp.async.cg.shared.global [%0], [%1], 16, %2;\n"
                         :: "r"(db), "l"(pb), "r"(pbytes));
        }
    };

    const int T = Kc / 32;
    issue(0, 0);
    asm volatile("cp.async.commit_group;\n" ::: "memory");

    for (int it = 0; it < T; ++it) {
        const int cur = it & 1;
        if (it + 1 < T) {
            issue(it + 1, (it + 1) & 1);
            asm volatile("cp.async.commit_group;\n" ::: "memory");
            asm volatile("cp.async.wait_group 1;\n" ::: "memory");
        } else {
            asm volatile("cp.async.wait_group 0;\n" ::: "memory");
        }
        __syncthreads();

        const float* AS = AsBase + cur * 4096;
        const float* BS = BsBase + cur * 4096;
        #pragma unroll
        for (int kk = 0; kk < 32; kk += 8) {
            unsigned af[4][4], bf[4][2];
            #pragma unroll
            for (int mi = 0; mi < 4; mi++) {
                const int rr = wm + mi * 16 + qr;
                af[mi][0] = __float_as_uint(AS[SW(rr,     kk + qc)]);
                af[mi][1] = __float_as_uint(AS[SW(rr + 8, kk + qc)]);
                af[mi][2] = __float_as_uint(AS[SW(rr,     kk + qc + 4)]);
                af[mi][3] = __float_as_uint(AS[SW(rr + 8, kk + qc + 4)]);
            }
            #pragma unroll
            for (int ni = 0; ni < 4; ni++) {
                const int rr = wn + ni * 8 + qr;
                bf[ni][0] = __float_as_uint(BS[SW(rr, kk + qc)]);
                bf[ni][1] = __float_as_uint(BS[SW(rr, kk + qc + 4)]);
            }
            #pragma unroll
            for (int mi = 0; mi < 4; mi++)
                #pragma unroll
                for (int ni = 0; ni < 4; ni++)
                    mma8(acc[mi][ni], af[mi], bf[ni]);
        }
        __syncthreads();
    }

    #pragma unroll
    for (int mi = 0; mi < 4; mi++) {
        #pragma unroll
        for (int ni = 0; ni < 4; ni++) {
            const int row = m0 + wm + mi * 16 + qr;
            const int col = n0 + wn + ni * 8 + qc * 2;
            store_epi<EPI>(C, ldc, N, row,     col,     acc[mi][ni][0], bias, resid, mask);
            store_epi<EPI>(C, ldc, N, row,     col + 1, acc[mi][ni][1], bias, resid, mask);
            store_epi<EPI>(C, ldc, N, row + 8, col,     acc[mi][ni][2], bias, resid, mask);
            store_epi<EPI>(C, ldc, N, row + 8, col + 1, acc[mi][ni][3], bias, resid, mask);
        }
    }
}

// Sum the XSPLIT split-K partials of x_proj into g_xdbl.
__global__ __launch_bounds__(256) void reduce_xpart_kernel(
    const float* __restrict__ part, float* __restrict__ out)
{
    const int i = blockIdx.x * 256 + threadIdx.x;   // BL*NXC total
    float s = 0.f;
    #pragma unroll
    for (int z = 0; z < XSPLIT; z++)
        s += part[(size_t)z * (BL * NXC) + i];
    out[i] = s;
}

// ---------------------------------------------------------------------------
// Depthwise causal conv (segment-gated) + SiLU.
// gate_j == (mask[l-j..l] all valid). Tap weight = conv_w[d][3-j].
// One thread handles 4 channels of one (b,l).
// ---------------------------------------------------------------------------
__global__ __launch_bounds__(256) void conv_silu_kernel(
    const float* __restrict__ xz, const float* __restrict__ cw,
    const float* __restrict__ cb, const unsigned* __restrict__ mask,
    float* __restrict__ xc)
{
    const int t = blockIdx.x * 256 + threadIdx.x;   // BL * DI/4 threads
    const int m = t >> 9;                            // row (b*L+l)
    const int c4 = (t & 511) << 2;                   // channel base
    const int l = m & (SEQ - 1);

    const float4* cw4 = reinterpret_cast<const float4*>(cw);
    float4 W0 = cw4[c4 + 0], W1 = cw4[c4 + 1], W2 = cw4[c4 + 2], W3 = cw4[c4 + 3];
    float4 acc = *reinterpret_cast<const float4*>(cb + c4);

    bool g0 = mask[m] != 0;
    bool g1 = g0 && l >= 1 && mask[m - 1] != 0;
    bool g2 = g1 && l >= 2 && mask[m - 2] != 0;
    bool g3 = g2 && l >= 3 && mask[m - 3] != 0;

    const float4* xi = reinterpret_cast<const float4*>(xz); // row stride 1024 float4
    const int base = m * 1024 + (c4 >> 2);
    if (g0) { float4 xv = xi[base];
        acc.x += W0.w * xv.x; acc.y += W1.w * xv.y; acc.z += W2.w * xv.z; acc.w += W3.w * xv.w; }
    if (g1) { float4 xv = xi[base - 1024];
        acc.x += W0.z * xv.x; acc.y += W1.z * xv.y; acc.z += W2.z * xv.z; acc.w += W3.z * xv.w; }
    if (g2) { float4 xv = xi[base - 2048];
        acc.x += W0.y * xv.x; acc.y += W1.y * xv.y; acc.z += W2.y * xv.z; acc.w += W3.y * xv.w; }
    if (g3) { float4 xv = xi[base - 3072];
        acc.x += W0.x * xv.x; acc.y += W1.x * xv.y; acc.z += W2.x * xv.z; acc.w += W3.x * xv.w; }

    float4 o;
    o.x = acc.x / (1.f + __expf(-acc.x));
    o.y = acc.y / (1.f + __expf(-acc.y));
    o.z = acc.z / (1.f + __expf(-acc.z));
    o.w = acc.w / (1.f + __expf(-acc.w));
    reinterpret_cast<float4*>(xc)[m * 512 + (c4 >> 2)] = o;
}

// ---------------------------------------------------------------------------
// Selective scan. Block = 256 threads = 16 channels x 16 states.
// Grid = B * DI/16 = 512 blocks. Thread owns h[d][s] over L steps; step l+1's
// loads are issued before step l's exp->fma->shfl chain (software pipeline).
// ---------------------------------------------------------------------------
__global__ __launch_bounds__(256) void scan_kernel(
    const float* __restrict__ xz, const float* __restrict__ xc,
    const float* __restrict__ xdbl, const float* __restrict__ dt,
    const float* __restrict__ A_log, const float* __restrict__ Dp,
    const unsigned* __restrict__ mask, float* __restrict__ ybuf)
{
    const int blk = blockIdx.x;
    const int b = blk >> 7;           // / (DI/16)
    const int cg = blk & 127;
    const int s = threadIdx.x & 15;
    const int ci = threadIdx.x >> 4;
    const int d = cg * 16 + ci;

    const float Aval = -expf(A_log[d * DS + s]);
    const float Dv = Dp[d];
    float h = 0.f;
    const int mbase = b * SEQ;

    int m = mbase;
    float dtv = dt[(size_t)m * DI + d];
    float xv  = xc[(size_t)m * DI + d];
    float Bv  = xdbl[m * NXC + DTRK + s];
    float Cv  = xdbl[m * NXC + DTRK + DS + s];
    unsigned mk = mask[m];

    for (int l = 0; l < SEQ; l++) {
        float ndt = 0.f, nx = 0.f, nB = 0.f, nC = 0.f;
        unsigned nm = 0u;
        if (l + 1 < SEQ) {
            const int m2 = m + 1;
            ndt = dt[(size_t)m2 * DI + d];
            nx  = xc[(size_t)m2 * DI + d];
            nB  = xdbl[m2 * NXC + DTRK + s];
            nC  = xdbl[m2 * NXC + DTRK + DS + s];
            nm  = mask[m2];
        }

        float dA = __expf(dtv * Aval);
        h = mk ? fmaf(dA, h, dtv * Bv * xv) : 0.f;
        float yp = h * Cv;
        yp += __shfl_xor_sync(0xffffffffu, yp, 1);
        yp += __shfl_xor_sync(0xffffffffu, yp, 2);
        yp += __shfl_xor_sync(0xffffffffu, yp, 4);
        yp += __shfl_xor_sync(0xffffffffu, yp, 8);
        if (s == 0) {
            float zv = xz[(size_t)m * (2 * DI) + DI + d];
            float y = yp + Dv * xv;
            ybuf[(size_t)m * DI + d] = y * (zv / (1.f + __expf(-zv)));
        }

        dtv = ndt; xv = nx; Bv = nB; Cv = nC; mk = nm;
        m++;
    }
}

// ---------------------------------------------------------------------------
// Launch
// ---------------------------------------------------------------------------
extern "C" void kernel_launch(void* const* d_in, const int* in_sizes, int n_in,
                              void* d_out, int out_size)
{
    (void)in_sizes; (void)n_in; (void)out_size;
    const float*    x         = (const float*)d_in[0];
    const unsigned* mask      = (const unsigned*)d_in[1];   // bool as 32-bit word, != 0
    const float*    rms_w     = (const float*)d_in[2];
    const float*    in_proj_w = (const float*)d_in[3];
    const float*    conv_w    = (const float*)d_in[4];
    const float*    conv_b    = (const float*)d_in[5];
    const float*    x_proj_w  = (const float*)d_in[6];
    const float*    dt_proj_w = (const float*)d_in[7];
    const float*    dt_proj_b = (const float*)d_in[8];
    const float*    A_log     = (const float*)d_in[9];
    const float*    Dp        = (const float*)d_in[10];
    const float*    out_proj_w= (const float*)d_in[11];
    float*          out       = (float*)d_out;

    float *normed, *xzb, *xcb, *xdblb, *xpartb, *dtb, *yb;
    cudaGetSymbolAddress((void**)&normed, g_normed);
    cudaGetSymbolAddress((void**)&xzb,    g_xz);
    cudaGetSymbolAddress((void**)&xcb,    g_xc);
    cudaGetSymbolAddress((void**)&xdblb,  g_xdbl);
    cudaGetSymbolAddress((void**)&xpartb, g_xpart);
    cudaGetSymbolAddress((void**)&dtb,    g_dt);
    cudaGetSymbolAddress((void**)&yb,     g_y);

    const int SMEM = 16384 * 4;   // 64 KB dynamic
    cudaFuncSetAttribute(gemm_tf32<0, 1>,      cudaFuncAttributeMaxDynamicSharedMemorySize, SMEM);
    cudaFuncSetAttribute(gemm_tf32<0, XSPLIT>, cudaFuncAttributeMaxDynamicSharedMemorySize, SMEM);
    cudaFuncSetAttribute(gemm_tf32<1, 1>,      cudaFuncAttributeMaxDynamicSharedMemorySize, SMEM);
    cudaFuncSetAttribute(gemm_tf32<2, 1>,      cudaFuncAttributeMaxDynamicSharedMemorySize, SMEM);

    // 1. RMSNorm
    rmsnorm_kernel<<<BL, 256>>>(x, rms_w, normed);

    // 2. in_proj: xz[BL,4096] = normed[BL,1024] @ in_proj_w[4096,1024]^T
    gemm_tf32<0, 1><<<dim3(32, 32), 256, SMEM>>>(normed, DM, in_proj_w, DM,
                                                 xzb, 2 * DI, BL, 2 * DI, DM,
                                                 nullptr, nullptr, nullptr);

    // 3. segment-gated causal conv + SiLU -> x_c[BL,2048]
    conv_silu_kernel<<<(BL * (DI / 4)) / 256, 256>>>(xzb, conv_w, conv_b, mask, xcb);

    // 4. x_proj split-K: partials[z][BL,96] = x_c @ x_proj_w[96,2048]^T (K chunk z)
    gemm_tf32<0, XSPLIT><<<dim3(1, 32, XSPLIT), 256, SMEM>>>(
        xcb, DI, x_proj_w, DI, xpartb, NXC, BL, NXC, DI,
        nullptr, nullptr, nullptr);
    reduce_xpart_kernel<<<(BL * NXC) / 256, 256>>>(xpartb, xdblb);

    // 5. dt: softplus(x_dbl[:, :64] @ dt_proj_w[2048,64]^T + b) -> dt[BL,2048]
    gemm_tf32<1, 1><<<dim3(16, 32), 256, SMEM>>>(xdblb, NXC, dt_proj_w, DTRK,
                                                 dtb, DI, BL, DI, DTRK,
                                                 dt_proj_b, nullptr, nullptr);

    // 6. selective scan (+ D*x_c, * silu(z)) -> y[BL,2048]
    scan_kernel<<<BATCH * (DI / 16), 256>>>(xzb, xcb, xdblb, dtb, A_log, Dp, mask, yb);

    // 7. out_proj + residual + mask: out = mask ? x + y @ out_proj_w^T : 0
    gemm_tf32<2, 1><<<dim3(8, 32), 256, SMEM>>>(yb, DI, out_proj_w, DI,
                                                out, DM, BL, DM, DI,
                                                nullptr, x, mask);
}